// round 9
// baseline (speedup 1.0000x reference)
#include <cuda_runtime.h>
#include <cuda_fp16.h>
#include <cstdint>

// ===========================================================================
// Problem constants
// ===========================================================================
#define N_NODES 100000
#define N_EDGES 200000
#define DIM     256
#define NB      2
#define NC      8
#define TCOLS   (NB * DIM)   // 512

// Scratch (device globals: allocation-guard safe)
__device__ __half g_tf[(size_t)N_NODES * TCOLS];   // t fp16, 102.4 MB
__device__ __half g_bf[(size_t)TCOLS * DIM];       // B fp16 [n][k], n=b*256+j

// ===========================================================================
// Baseline-PTX helpers (sm_80-class only — no 'a' features!)
// ===========================================================================
__device__ __forceinline__ uint32_t smem_u32(const void* p) {
    uint32_t a;
    asm("{ .reg .u64 t; cvta.to.shared.u64 t, %1; cvt.u32.u64 %0, t; }"
        : "=r"(a) : "l"(p));
    return a;
}

#define SWZ(off) ((uint32_t)(off) ^ ((((uint32_t)(off)) >> 3) & 0x70u))

#define CP_ASYNC16(dst, src) \
    asm volatile("cp.async.cg.shared.global [%0], [%1], 16;" \
        :: "r"(dst), "l"(src) : "memory")
#define CP_COMMIT() asm volatile("cp.async.commit_group;" ::: "memory")
#define CP_WAIT(n)  asm volatile("cp.async.wait_group %0;" :: "n"(n) : "memory")

#define LDSM_X4(r0, r1, r2, r3, addr) \
    asm volatile("ldmatrix.sync.aligned.m8n8.x4.shared.b16 {%0,%1,%2,%3}, [%4];" \
        : "=r"(r0), "=r"(r1), "=r"(r2), "=r"(r3) : "r"(addr))

#define MMA_F16(c, a, b0, b1) \
    asm volatile("mma.sync.aligned.m16n8k16.row.col.f32.f16.f16.f32 " \
        "{%0,%1,%2,%3}, {%4,%5,%6,%7}, {%8,%9}, {%0,%1,%2,%3};" \
        : "+f"((c)[0]), "+f"((c)[1]), "+f"((c)[2]), "+f"((c)[3]) \
        : "r"((a)[0]), "r"((a)[1]), "r"((a)[2]), "r"((a)[3]), "r"(b0), "r"(b1))

// ===========================================================================
// Kernel 0: transpose P -> g_bf fp16, [n][k], n = b*256 + j
// ===========================================================================
__global__ __launch_bounds__(256) void prep_B(const float* __restrict__ P)
{
    int idx = blockIdx.x * blockDim.x + threadIdx.x;
    if (idx >= NB * DIM * DIM) return;
    int b = idx >> 16;
    int k = (idx >> 8) & 255;
    int j = idx & 255;
    int n = b * DIM + j;
    g_bf[(size_t)n * DIM + k] = __float2half_rn(P[idx]);
}

// ===========================================================================
// Kernel 1: fused-convert fp16 mma.sync GEMM
//   t[100000, 512] = A_fp32[100000,256] @ B^T  (B fp16 [n][k]), output fp16
// Tiles: BM=128, BN=128, BK=64. B SMEM-resident (64KB, cp.async).
// A: fp32 LDG -> in-register fp16 convert -> STS, 2-stage double buffer,
// half-stage sub-phases to bound register pressure. 96KB SMEM -> 2 CTA/SM.
// ===========================================================================
static constexpr int A_STAGE_BYTES = 16384;            // 128 rows x 128B fp16
static constexpr int B_PANEL_BYTES = 16384;            // 128 rows x 128B
static constexpr int SM_B = 2 * A_STAGE_BYTES;         // 32768
static constexpr int SMEM_TOTAL = SM_B + 65536;        // 98304 (96 KB)

// Load half of an A stage (64 rows) into registers: 16 fp32 per thread.
__device__ __forceinline__ void lda_regs(const float* __restrict__ A,
                                         int m0, int kc, int h, int tid,
                                         float4 R[4])
{
    int row = 64 * h + (tid >> 2);          // 0..127
    int gr = m0 + row;
    if (gr >= N_NODES) gr = N_NODES - 1;    // clamp (rows unused on store)
    const float4* p = reinterpret_cast<const float4*>(
        A + (size_t)gr * DIM + kc * 64 + (tid & 3) * 16);
    R[0] = p[0]; R[1] = p[1]; R[2] = p[2]; R[3] = p[3];
}

// Convert + store that half-stage into swizzled fp16 SMEM.
__device__ __forceinline__ void sta_regs(char* smem, uint32_t buf_off,
                                         int h, int tid, const float4 R[4])
{
    int row = 64 * h + (tid >> 2);
    uint32_t base = (uint32_t)row * 128 + (uint32_t)(tid & 3) * 32;

    __half2 h0 = __floats2half2_rn(R[0].x, R[0].y);
    __half2 h1 = __floats2half2_rn(R[0].z, R[0].w);
    __half2 h2 = __floats2half2_rn(R[1].x, R[1].y);
    __half2 h3 = __floats2half2_rn(R[1].z, R[1].w);
    __half2 h4 = __floats2half2_rn(R[2].x, R[2].y);
    __half2 h5 = __floats2half2_rn(R[2].z, R[2].w);
    __half2 h6 = __floats2half2_rn(R[3].x, R[3].y);
    __half2 h7 = __floats2half2_rn(R[3].z, R[3].w);

    *reinterpret_cast<uint4*>(smem + buf_off + SWZ(base)) =
        make_uint4(*(uint32_t*)&h0, *(uint32_t*)&h1,
                   *(uint32_t*)&h2, *(uint32_t*)&h3);
    *reinterpret_cast<uint4*>(smem + buf_off + SWZ(base + 16)) =
        make_uint4(*(uint32_t*)&h4, *(uint32_t*)&h5,
                   *(uint32_t*)&h6, *(uint32_t*)&h7);
}

__global__ __launch_bounds__(256, 2) void gemm_mma(const float* __restrict__ A)
{
    extern __shared__ char smem[];
    const uint32_t sb  = smem_u32(smem);
    const uint32_t sbA = sb;
    const uint32_t sbB = sb + SM_B;

    const int tid  = threadIdx.x;
    const int lane = tid & 31;
    const int wid  = tid >> 5;
    const int warp_m = wid & 3;       // 4 warps along M (32 rows each)
    const int warp_n = wid >> 2;      // 2 warps along N (64 cols each)
    const int m0 = blockIdx.y * 128;
    const int n0 = blockIdx.x * 128;

    // ---- prologue: B via cp.async (resident all 4 k-panels)
#pragma unroll
    for (int i = 0; i < 16; i++) {
        int c  = tid + i * 256;          // 0..4095
        int n  = c >> 5;                 // n row 0..127
        int ck = c & 31;                 // 16B chunk within 512B row
        int kp = ck >> 3;                // k panel 0..3
        int cb = (ck & 7) * 16;          // col byte within panel row
        size_t goff = (size_t)(n0 + n) * DIM + ck * 8;
        uint32_t soff = (uint32_t)kp * B_PANEL_BYTES + SWZ(n * 128 + cb);
        CP_ASYNC16(sbB + soff, g_bf + goff);
    }
    CP_COMMIT();

    // ---- prologue: A stage 0 (LDG fp32 -> cvt -> STS fp16)
    float4 R[4];
    lda_regs(A, m0, 0, 0, tid, R);
    sta_regs(smem, 0, 0, tid, R);
    lda_regs(A, m0, 0, 1, tid, R);
    sta_regs(smem, 0, 1, tid, R);

    CP_WAIT(0);
    __syncthreads();

    float acc[2][8][4];
#pragma unroll
    for (int t = 0; t < 2; t++)
#pragma unroll
        for (int j = 0; j < 8; j++)
#pragma unroll
            for (int q = 0; q < 4; q++) acc[t][j][q] = 0.0f;

    // ldmatrix lane address components
    const int quad  = lane >> 3;
    const int a_row = warp_m * 32 + (quad & 1) * 8 + (lane & 7);
    const int a_cb  = (quad >> 1) * 16;
    const int b_row = warp_n * 64 + (quad >> 1) * 8 + (lane & 7);
    const int b_cb  = (quad & 1) * 16;

    for (int kc = 0; kc < 4; kc++) {
        const uint32_t aS = sbA + (uint32_t)(kc & 1) * A_STAGE_BYTES;
        const uint32_t bS = sbB + (uint32_t)kc * B_PANEL_BYTES;
        const uint32_t nbuf = ((uint32_t)(kc + 1) & 1) * A_STAGE_BYTES;

        // early LDG for next stage, first half
        if (kc < 3) lda_regs(A, m0, kc + 1, 0, tid, R);

#pragma unroll
        for (int ks = 0; ks < 4; ks++) {
            uint32_t af[2][4], bf[4][4];
#pragma unroll
            for (int t = 0; t < 2; t++) {
                uint32_t off = SWZ((a_row + t * 16) * 128 + ks * 32 + a_cb);
                LDSM_X4(af[t][0], af[t][1], af[t][2], af[t][3], aS + off);
            }
#pragma unroll
            for (int j = 0; j < 4; j++) {
                uint32_t off = SWZ((b_row + j * 16) * 128 + ks * 32 + b_cb);
                LDSM_X4(bf[j][0], bf[j][1], bf[j][2], bf[j][3], bS + off);
            }
#pragma unroll
            for (int t = 0; t < 2; t++)
#pragma unroll
                for (int j = 0; j < 4; j++) {
                    MMA_F16(acc[t][2 * j],     af[t], bf[j][0], bf[j][1]);
                    MMA_F16(acc[t][2 * j + 1], af[t], bf[j][2], bf[j][3]);
                }

            // mid-kc: store first half of next stage, start second half LDG
            if (ks == 1 && kc < 3) {
                sta_regs(smem, nbuf, 0, tid, R);
                lda_regs(A, m0, kc + 1, 1, tid, R);
            }
        }

        if (kc < 3) sta_regs(smem, nbuf, 1, tid, R);
        __syncthreads();
    }

    // ---- epilogue: write t tile as fp16 to g_tf
    const int mb = m0 + warp_m * 32;
    const int nb = n0 + warp_n * 64;
    const int r0 = lane >> 2;
    const int c0 = (lane & 3) * 2;
#pragma unroll
    for (int t = 0; t < 2; t++) {
#pragma unroll
        for (int nt = 0; nt < 8; nt++) {
            int col = nb + nt * 8 + c0;
            int row = mb + t * 16 + r0;
            __half2 p01 = __floats2half2_rn(acc[t][nt][0], acc[t][nt][1]);
            __half2 p23 = __floats2half2_rn(acc[t][nt][2], acc[t][nt][3]);
            if (row < N_NODES)
                *reinterpret_cast<__half2*>(&g_tf[(size_t)row * TCOLS + col]) = p01;
            if (row + 8 < N_NODES)
                *reinterpret_cast<__half2*>(&g_tf[(size_t)(row + 8) * TCOLS + col]) = p23;
        }
    }
}

// ===========================================================================
// Kernel 2: per-edge gather + dot + combine.
// 2 edges per warp (16 lanes each) -> 8 independent 16B loads per lane (2x MLP).
// ===========================================================================
__device__ __forceinline__ float dot8h(uint4 q, float4 a, float4 b)
{
    float2 f;
    float s;
    f = __half22float2(*reinterpret_cast<__half2*>(&q.x));
    s = fmaf(f.x, a.x, f.y * a.y);
    f = __half22float2(*reinterpret_cast<__half2*>(&q.y));
    s = fmaf(f.x, a.z, fmaf(f.y, a.w, s));
    f = __half22float2(*reinterpret_cast<__half2*>(&q.z));
    s = fmaf(f.x, b.x, fmaf(f.y, b.y, s));
    f = __half22float2(*reinterpret_cast<__half2*>(&q.w));
    s = fmaf(f.x, b.z, fmaf(f.y, b.w, s));
    return s;
}

__global__ __launch_bounds__(256) void edge_bilinear(
    const float* __restrict__ h_dst,
    const int*   __restrict__ u_idx,
    const int*   __restrict__ v_idx,
    const float* __restrict__ W,
    float*       __restrict__ out)
{
    const int warp = (blockIdx.x * blockDim.x + threadIdx.x) >> 5;
    const int lane = threadIdx.x & 31;
    const int half = lane >> 4;
    const int sub  = lane & 15;
    const int e = warp * 2 + half;
    if (e >= N_EDGES) return;

    const int u = u_idx[e];
    const int v = v_idx[e];

    const uint4*  tu = reinterpret_cast<const uint4*>(g_tf + (size_t)u * TCOLS);
    const float4* dv = reinterpret_cast<const float4*>(h_dst + (size_t)v * DIM);

    // lane covers k in [16*sub, 16*sub+16) for both bases
    uint4 q0a = tu[2 * sub];           // basis 0, k 16sub..+7
    uint4 q0b = tu[2 * sub + 1];       // basis 0, k 16sub+8..+15
    uint4 q1a = tu[32 + 2 * sub];      // basis 1
    uint4 q1b = tu[33 + 2 * sub];
    float4 d0 = dv[4 * sub];
    float4 d1 = dv[4 * sub + 1];
    float4 d2 = dv[4 * sub + 2];
    float4 d3 = dv[4 * sub + 3];

    float s0 = dot8h(q0a, d0, d1) + dot8h(q0b, d2, d3);
    float s1 = dot8h(q1a, d0, d1) + dot8h(q1b, d2, d3);

#pragma unroll
    for (int off = 8; off > 0; off >>= 1) {
        s0 += __shfl_xor_sync(0xFFFFFFFFu, s0, off);
        s1 += __shfl_xor_sync(0xFFFFFFFFu, s1, off);
    }

    if (sub < NC) {
        float w0 = __ldg(W + sub * NB + 0);
        float w1 = __ldg(W + sub * NB + 1);
        out[(size_t)e * NC + sub] = fmaf(s0, w0, s1 * w1);
    }
}

// ===========================================================================
// Launch
// ===========================================================================
extern "C" void kernel_launch(void* const* d_in, const int* in_sizes, int n_in,
                              void* d_out, int out_size)
{
    const float* h_src = (const float*)d_in[0];
    const float* h_dst = (const float*)d_in[1];
    const int*   u_idx = (const int*)d_in[2];
    const int*   v_idx = (const int*)d_in[3];
    const float* P     = (const float*)d_in[4];
    const float* W     = (const float*)d_in[5];
    float* out = (float*)d_out;

    cudaFuncSetAttribute(gemm_mma,
                         cudaFuncAttributeMaxDynamicSharedMemorySize,
                         SMEM_TOTAL);

    // 0) convert P to fp16 (transposed)
    prep_B<<<(NB * DIM * DIM + 255) / 256, 256>>>(P);

    // 1) fused-convert tensor-core node transform -> g_tf
    {
        dim3 grid(TCOLS / 128, (N_NODES + 127) / 128);
        gemm_mma<<<grid, 256, SMEM_TOTAL>>>(h_src);
    }

    // 2) edge gather + bilinear dot + combine (2 edges/warp)
    {
        int edges_per_block = 16;   // 8 warps x 2 edges
        int blocks = (N_EDGES + edges_per_block - 1) / edges_per_block;
        edge_bilinear<<<blocks, 256>>>(h_dst, u_idx, v_idx, W, out);
    }
}

// round 10
// speedup vs baseline: 1.1685x; 1.1685x over previous
#include <cuda_runtime.h>
#include <cuda_fp16.h>
#include <cstdint>

// ===========================================================================
// Problem constants
// ===========================================================================
#define N_NODES 100000
#define N_EDGES 200000
#define DIM     256
#define NB      2
#define NC      8
#define TCOLS   (NB * DIM)   // 512

// Scratch (device globals: allocation-guard safe)
__device__ __half g_tf[(size_t)N_NODES * TCOLS];   // t fp16, 102.4 MB
__device__ __half g_af[(size_t)N_NODES * DIM];     // A fp16 [node][k]
__device__ __half g_bf[(size_t)TCOLS * DIM];       // B fp16 [n][k], n=b*256+j

// ===========================================================================
// Baseline-PTX helpers (sm_80-class only — no 'a' features!)
// ===========================================================================
__device__ __forceinline__ uint32_t smem_u32(const void* p) {
    uint32_t a;
    asm("{ .reg .u64 t; cvta.to.shared.u64 t, %1; cvt.u32.u64 %0, t; }"
        : "=r"(a) : "l"(p));
    return a;
}

#define SWZ(off) ((uint32_t)(off) ^ ((((uint32_t)(off)) >> 3) & 0x70u))

#define CP_ASYNC16(dst, src) \
    asm volatile("cp.async.cg.shared.global [%0], [%1], 16;" \
        :: "r"(dst), "l"(src) : "memory")
#define CP_COMMIT() asm volatile("cp.async.commit_group;" ::: "memory")
#define CP_WAIT(n)  asm volatile("cp.async.wait_group %0;" :: "n"(n) : "memory")

#define LDSM_X4(r0, r1, r2, r3, addr) \
    asm volatile("ldmatrix.sync.aligned.m8n8.x4.shared.b16 {%0,%1,%2,%3}, [%4];" \
        : "=r"(r0), "=r"(r1), "=r"(r2), "=r"(r3) : "r"(addr))

#define MMA_F16(c, a, b0, b1) \
    asm volatile("mma.sync.aligned.m16n8k16.row.col.f32.f16.f16.f32 " \
        "{%0,%1,%2,%3}, {%4,%5,%6,%7}, {%8,%9}, {%0,%1,%2,%3};" \
        : "+f"((c)[0]), "+f"((c)[1]), "+f"((c)[2]), "+f"((c)[3]) \
        : "r"((a)[0]), "r"((a)[1]), "r"((a)[2]), "r"((a)[3]), "r"(b0), "r"(b1))

// ===========================================================================
// Kernel 0a: A (h_src fp32) -> g_af fp16
// ===========================================================================
__global__ __launch_bounds__(256) void prep_A(const float* __restrict__ A)
{
    int idx = blockIdx.x * blockDim.x + threadIdx.x;     // per float4
    if (idx >= N_NODES * (DIM / 4)) return;
    float4 v = reinterpret_cast<const float4*>(A)[idx];
    __half2 p01 = __floats2half2_rn(v.x, v.y);
    __half2 p23 = __floats2half2_rn(v.z, v.w);
    reinterpret_cast<uint2*>(g_af)[idx] =
        make_uint2(*(uint32_t*)&p01, *(uint32_t*)&p23);
}

// ===========================================================================
// Kernel 0b: transpose P -> g_bf fp16, [n][k], n = b*256 + j
// ===========================================================================
__global__ __launch_bounds__(256) void prep_B(const float* __restrict__ P)
{
    int idx = blockIdx.x * blockDim.x + threadIdx.x;
    if (idx >= NB * DIM * DIM) return;
    int b = idx >> 16;
    int k = (idx >> 8) & 255;
    int j = idx & 255;
    int n = b * DIM + j;
    g_bf[(size_t)n * DIM + k] = __float2half_rn(P[idx]);
}

// ===========================================================================
// Kernel 1: single-pass fp16 mma.sync GEMM  (R8 version — known best)
//   t[100000, 512] = A[100000,256] @ B^T   (B stored [n][k]), output fp16
// Tiles: BM=128, BN=128, BK=64. B fully SMEM-resident (64KB).
// A fp16 streamed via cp.async, 3 stages (16KB each), prefetch distance 2.
// SMEM total 112KB -> 2 CTAs/SM.
// ===========================================================================
static constexpr int A_STAGE_BYTES = 16384;            // 128 rows x 128B
static constexpr int B_PANEL_BYTES = 16384;            // 128 rows x 128B
static constexpr int SM_B  = 3 * A_STAGE_BYTES;        // 49152
static constexpr int SMEM_TOTAL = SM_B + 65536;        // 114688 (112 KB)

__device__ __forceinline__ void load_A_stage(uint32_t sbA, int m0, int kc,
                                             int buf, int tid)
{
    const uint32_t base = sbA + buf * A_STAGE_BYTES;
#pragma unroll
    for (int i = 0; i < 4; i++) {
        int c  = tid + i * 256;           // 0..1023 (16B chunks)
        int r  = c >> 3;                  // row 0..127
        int ck = c & 7;                   // chunk in 128B row
        int gr = m0 + r;
        if (gr >= N_NODES) gr = N_NODES - 1;     // clamp (rows unused on store)
        size_t goff = (size_t)gr * DIM + kc * 64 + ck * 8;
        uint32_t soff = SWZ(r * 128 + ck * 16);
        CP_ASYNC16(base + soff, g_af + goff);
    }
}

__global__ __launch_bounds__(256, 2) void gemm_mma()
{
    extern __shared__ char smem[];
    const uint32_t sb   = smem_u32(smem);
    const uint32_t sbA  = sb;
    const uint32_t sbB  = sb + SM_B;

    const int tid  = threadIdx.x;
    const int lane = tid & 31;
    const int wid  = tid >> 5;
    const int warp_m = wid & 3;       // 4 warps along M (32 rows each)
    const int warp_n = wid >> 2;      // 2 warps along N (64 cols each)
    const int m0 = blockIdx.y * 128;
    const int n0 = blockIdx.x * 128;

    // ---- prologue: B (resident) + A stage 0 -> group0; A stage 1 -> group1
#pragma unroll
    for (int i = 0; i < 16; i++) {
        int c  = tid + i * 256;          // 0..4095
        int n  = c >> 5;                 // n row 0..127
        int ck = c & 31;                 // 16B chunk within 512B row
        int kp = ck >> 3;                // k panel 0..3
        int cb = (ck & 7) * 16;          // col byte within panel row
        size_t goff = (size_t)(n0 + n) * DIM + ck * 8;
        uint32_t soff = (uint32_t)kp * B_PANEL_BYTES + SWZ(n * 128 + cb);
        CP_ASYNC16(sbB + soff, g_bf + goff);
    }
    load_A_stage(sbA, m0, 0, 0, tid);
    CP_COMMIT();
    load_A_stage(sbA, m0, 1, 1, tid);
    CP_COMMIT();

    float acc[2][8][4];
#pragma unroll
    for (int t = 0; t < 2; t++)
#pragma unroll
        for (int j = 0; j < 8; j++)
#pragma unroll
            for (int q = 0; q < 4; q++) acc[t][j][q] = 0.0f;

    // ldmatrix lane address components
    const int quad  = lane >> 3;
    const int a_row = warp_m * 32 + (quad & 1) * 8 + (lane & 7);
    const int a_cb  = (quad >> 1) * 16;
    const int b_row = warp_n * 64 + (quad >> 1) * 8 + (lane & 7);
    const int b_cb  = (quad & 1) * 16;

    for (int kc = 0; kc < 4; kc++) {
        if (kc < 3) { CP_WAIT(1); } else { CP_WAIT(0); }
        __syncthreads();
        if (kc + 2 <= 3) {
            load_A_stage(sbA, m0, kc + 2, (kc + 2) % 3, tid);
            CP_COMMIT();
        }

        const uint32_t aS = sbA + (uint32_t)(kc % 3) * A_STAGE_BYTES;
        const uint32_t bS = sbB + (uint32_t)kc * B_PANEL_BYTES;

#pragma unroll
        for (int ks = 0; ks < 4; ks++) {
            uint32_t af[2][4], bf[4][4];
#pragma unroll
            for (int t = 0; t < 2; t++) {
                uint32_t off = SWZ((a_row + t * 16) * 128 + ks * 32 + a_cb);
                LDSM_X4(af[t][0], af[t][1], af[t][2], af[t][3], aS + off);
            }
#pragma unroll
            for (int j = 0; j < 4; j++) {
                uint32_t off = SWZ((b_row + j * 16) * 128 + ks * 32 + b_cb);
                LDSM_X4(bf[j][0], bf[j][1], bf[j][2], bf[j][3], bS + off);
            }
#pragma unroll
            for (int t = 0; t < 2; t++)
#pragma unroll
                for (int j = 0; j < 4; j++) {
                    MMA_F16(acc[t][2 * j],     af[t], bf[j][0], bf[j][1]);
                    MMA_F16(acc[t][2 * j + 1], af[t], bf[j][2], bf[j][3]);
                }
        }
    }

    // ---- epilogue: write t tile as fp16 to g_tf
    const int mb = m0 + warp_m * 32;
    const int nb = n0 + warp_n * 64;
    const int r0 = lane >> 2;
    const int c0 = (lane & 3) * 2;
#pragma unroll
    for (int t = 0; t < 2; t++) {
#pragma unroll
        for (int nt = 0; nt < 8; nt++) {
            int col = nb + nt * 8 + c0;
            int row = mb + t * 16 + r0;
            __half2 p01 = __floats2half2_rn(acc[t][nt][0], acc[t][nt][1]);
            __half2 p23 = __floats2half2_rn(acc[t][nt][2], acc[t][nt][3]);
            if (row < N_NODES)
                *reinterpret_cast<__half2*>(&g_tf[(size_t)row * TCOLS + col]) = p01;
            if (row + 8 < N_NODES)
                *reinterpret_cast<__half2*>(&g_tf[(size_t)(row + 8) * TCOLS + col]) = p23;
        }
    }
}

// ===========================================================================
// Kernel 2: per-edge gather + dot + combine.
// 2 edges per warp (16 lanes each) -> 8 independent 16B loads per lane (2x MLP).
// ===========================================================================
__device__ __forceinline__ float dot8h(uint4 q, float4 a, float4 b)
{
    float2 f;
    float s;
    f = __half22float2(*reinterpret_cast<__half2*>(&q.x));
    s = fmaf(f.x, a.x, f.y * a.y);
    f = __half22float2(*reinterpret_cast<__half2*>(&q.y));
    s = fmaf(f.x, a.z, fmaf(f.y, a.w, s));
    f = __half22float2(*reinterpret_cast<__half2*>(&q.z));
    s = fmaf(f.x, b.x, fmaf(f.y, b.y, s));
    f = __half22float2(*reinterpret_cast<__half2*>(&q.w));
    s = fmaf(f.x, b.z, fmaf(f.y, b.w, s));
    return s;
}

__global__ __launch_bounds__(256) void edge_bilinear(
    const float* __restrict__ h_dst,
    const int*   __restrict__ u_idx,
    const int*   __restrict__ v_idx,
    const float* __restrict__ W,
    float*       __restrict__ out)
{
    const int warp = (blockIdx.x * blockDim.x + threadIdx.x) >> 5;
    const int lane = threadIdx.x & 31;
    const int half = lane >> 4;
    const int sub  = lane & 15;
    const int e = warp * 2 + half;
    if (e >= N_EDGES) return;

    const int u = u_idx[e];
    const int v = v_idx[e];

    const uint4*  tu = reinterpret_cast<const uint4*>(g_tf + (size_t)u * TCOLS);
    const float4* dv = reinterpret_cast<const float4*>(h_dst + (size_t)v * DIM);

    // lane covers k in [16*sub, 16*sub+16) for both bases
    uint4 q0a = tu[2 * sub];           // basis 0, k 16sub..+7
    uint4 q0b = tu[2 * sub + 1];       // basis 0, k 16sub+8..+15
    uint4 q1a = tu[32 + 2 * sub];      // basis 1
    uint4 q1b = tu[33 + 2 * sub];
    float4 d0 = dv[4 * sub];
    float4 d1 = dv[4 * sub + 1];
    float4 d2 = dv[4 * sub + 2];
    float4 d3 = dv[4 * sub + 3];

    float s0 = dot8h(q0a, d0, d1) + dot8h(q0b, d2, d3);
    float s1 = dot8h(q1a, d0, d1) + dot8h(q1b, d2, d3);

#pragma unroll
    for (int off = 8; off > 0; off >>= 1) {
        s0 += __shfl_xor_sync(0xFFFFFFFFu, s0, off);
        s1 += __shfl_xor_sync(0xFFFFFFFFu, s1, off);
    }

    if (sub < NC) {
        float w0 = __ldg(W + sub * NB + 0);
        float w1 = __ldg(W + sub * NB + 1);
        out[(size_t)e * NC + sub] = fmaf(s0, w0, s1 * w1);
    }
}

// ===========================================================================
// Launch
// ===========================================================================
extern "C" void kernel_launch(void* const* d_in, const int* in_sizes, int n_in,
                              void* d_out, int out_size)
{
    const float* h_src = (const float*)d_in[0];
    const float* h_dst = (const float*)d_in[1];
    const int*   u_idx = (const int*)d_in[2];
    const int*   v_idx = (const int*)d_in[3];
    const float* P     = (const float*)d_in[4];
    const float* W     = (const float*)d_in[5];
    float* out = (float*)d_out;

    cudaFuncSetAttribute(gemm_mma,
                         cudaFuncAttributeMaxDynamicSharedMemorySize,
                         SMEM_TOTAL);

    // 0) convert inputs to fp16
    prep_A<<<(N_NODES * (DIM / 4) + 255) / 256, 256>>>(h_src);
    prep_B<<<(NB * DIM * DIM + 255) / 256, 256>>>(P);

    // 1) tensor-core node transform -> g_tf  (grid: n fastest for L2 A-reuse)
    {
        dim3 grid(TCOLS / 128, (N_NODES + 127) / 128);
        gemm_mma<<<grid, 256, SMEM_TOTAL>>>();
    }

    // 2) edge gather + bilinear dot + combine (2 edges/warp)
    {
        int edges_per_block = 16;   // 8 warps x 2 edges
        int blocks = (N_EDGES + edges_per_block - 1) / edges_per_block;
        edge_bilinear<<<blocks, 256>>>(h_dst, u_idx, v_idx, W, out);
    }
}

// round 11
// speedup vs baseline: 1.1992x; 1.0262x over previous
#include <cuda_runtime.h>
#include <cuda_fp16.h>
#include <cstdint>

// ===========================================================================
// Problem constants
// ===========================================================================
#define N_NODES 100000
#define N_EDGES 200000
#define DIM     256
#define NB      2
#define NC      8
#define TCOLS   (NB * DIM)   // 512

// Scratch (device globals: allocation-guard safe)
__device__ __half g_tf[(size_t)N_NODES * TCOLS];   // t fp16, 102.4 MB
__device__ __half g_af[(size_t)N_NODES * DIM];     // A fp16 [node][k]
__device__ __half g_bf[(size_t)TCOLS * DIM];       // B fp16 [n][k], n=b*256+j

// ===========================================================================
// Baseline-PTX helpers (sm_80-class only — no 'a' features!)
// ===========================================================================
__device__ __forceinline__ uint32_t smem_u32(const void* p) {
    uint32_t a;
    asm("{ .reg .u64 t; cvta.to.shared.u64 t, %1; cvt.u32.u64 %0, t; }"
        : "=r"(a) : "l"(p));
    return a;
}

#define SWZ(off) ((uint32_t)(off) ^ ((((uint32_t)(off)) >> 3) & 0x70u))

#define CP_ASYNC16(dst, src) \
    asm volatile("cp.async.cg.shared.global [%0], [%1], 16;" \
        :: "r"(dst), "l"(src) : "memory")
#define CP_COMMIT() asm volatile("cp.async.commit_group;" ::: "memory")
#define CP_WAIT(n)  asm volatile("cp.async.wait_group %0;" :: "n"(n) : "memory")

#define LDSM_X4(r0, r1, r2, r3, addr) \
    asm volatile("ldmatrix.sync.aligned.m8n8.x4.shared.b16 {%0,%1,%2,%3}, [%4];" \
        : "=r"(r0), "=r"(r1), "=r"(r2), "=r"(r3) : "r"(addr))

#define MMA_F16(c, a, b0, b1) \
    asm volatile("mma.sync.aligned.m16n8k16.row.col.f32.f16.f16.f32 " \
        "{%0,%1,%2,%3}, {%4,%5,%6,%7}, {%8,%9}, {%0,%1,%2,%3};" \
        : "+f"((c)[0]), "+f"((c)[1]), "+f"((c)[2]), "+f"((c)[3]) \
        : "r"((a)[0]), "r"((a)[1]), "r"((a)[2]), "r"((a)[3]), "r"(b0), "r"(b1))

// ===========================================================================
// Kernel 0: fused prep — A (h_src fp32 -> g_af fp16) and P -> g_bf (transposed)
// Blocks [0, A_BLOCKS): A conversion. Blocks [A_BLOCKS, A_BLOCKS+B_BLOCKS): P.
// ===========================================================================
static constexpr int A_ITEMS  = N_NODES * (DIM / 4);      // float4 units
static constexpr int A_BLOCKS = (A_ITEMS + 255) / 256;    // 25000
static constexpr int B_ITEMS  = NB * DIM * DIM;
static constexpr int B_BLOCKS = (B_ITEMS + 255) / 256;    // 512

__global__ __launch_bounds__(256) void prep_fused(const float* __restrict__ A,
                                                  const float* __restrict__ P)
{
    if (blockIdx.x < A_BLOCKS) {
        int idx = blockIdx.x * 256 + threadIdx.x;
        if (idx >= A_ITEMS) return;
        float4 v = reinterpret_cast<const float4*>(A)[idx];
        __half2 p01 = __floats2half2_rn(v.x, v.y);
        __half2 p23 = __floats2half2_rn(v.z, v.w);
        reinterpret_cast<uint2*>(g_af)[idx] =
            make_uint2(*(uint32_t*)&p01, *(uint32_t*)&p23);
    } else {
        int idx = (blockIdx.x - A_BLOCKS) * 256 + threadIdx.x;
        if (idx >= B_ITEMS) return;
        int b = idx >> 16;
        int k = (idx >> 8) & 255;
        int j = idx & 255;
        int n = b * DIM + j;
        g_bf[(size_t)n * DIM + k] = __float2half_rn(P[idx]);
    }
}

// ===========================================================================
// Kernel 1: single-pass fp16 mma.sync GEMM  (R8 version — known best)
//   t[100000, 512] = A[100000,256] @ B^T   (B stored [n][k]), output fp16
// Tiles: BM=128, BN=128, BK=64. B fully SMEM-resident (64KB).
// A fp16 streamed via cp.async, 3 stages (16KB each), prefetch distance 2.
// SMEM total 112KB -> 2 CTAs/SM.
// ===========================================================================
static constexpr int A_STAGE_BYTES = 16384;            // 128 rows x 128B
static constexpr int B_PANEL_BYTES = 16384;            // 128 rows x 128B
static constexpr int SM_B  = 3 * A_STAGE_BYTES;        // 49152
static constexpr int SMEM_TOTAL = SM_B + 65536;        // 114688 (112 KB)

__device__ __forceinline__ void load_A_stage(uint32_t sbA, int m0, int kc,
                                             int buf, int tid)
{
    const uint32_t base = sbA + buf * A_STAGE_BYTES;
#pragma unroll
    for (int i = 0; i < 4; i++) {
        int c  = tid + i * 256;           // 0..1023 (16B chunks)
        int r  = c >> 3;                  // row 0..127
        int ck = c & 7;                   // chunk in 128B row
        int gr = m0 + r;
        if (gr >= N_NODES) gr = N_NODES - 1;     // clamp (rows unused on store)
        size_t goff = (size_t)gr * DIM + kc * 64 + ck * 8;
        uint32_t soff = SWZ(r * 128 + ck * 16);
        CP_ASYNC16(base + soff, g_af + goff);
    }
}

__global__ __launch_bounds__(256, 2) void gemm_mma()
{
    extern __shared__ char smem[];
    const uint32_t sb   = smem_u32(smem);
    const uint32_t sbA  = sb;
    const uint32_t sbB  = sb + SM_B;

    const int tid  = threadIdx.x;
    const int lane = tid & 31;
    const int wid  = tid >> 5;
    const int warp_m = wid & 3;       // 4 warps along M (32 rows each)
    const int warp_n = wid >> 2;      // 2 warps along N (64 cols each)
    const int m0 = blockIdx.y * 128;
    const int n0 = blockIdx.x * 128;

    // ---- prologue: B (resident) + A stage 0 -> group0; A stage 1 -> group1
#pragma unroll
    for (int i = 0; i < 16; i++) {
        int c  = tid + i * 256;          // 0..4095
        int n  = c >> 5;                 // n row 0..127
        int ck = c & 31;                 // 16B chunk within 512B row
        int kp = ck >> 3;                // k panel 0..3
        int cb = (ck & 7) * 16;          // col byte within panel row
        size_t goff = (size_t)(n0 + n) * DIM + ck * 8;
        uint32_t soff = (uint32_t)kp * B_PANEL_BYTES + SWZ(n * 128 + cb);
        CP_ASYNC16(sbB + soff, g_bf + goff);
    }
    load_A_stage(sbA, m0, 0, 0, tid);
    CP_COMMIT();
    load_A_stage(sbA, m0, 1, 1, tid);
    CP_COMMIT();

    float acc[2][8][4];
#pragma unroll
    for (int t = 0; t < 2; t++)
#pragma unroll
        for (int j = 0; j < 8; j++)
#pragma unroll
            for (int q = 0; q < 4; q++) acc[t][j][q] = 0.0f;

    // ldmatrix lane address components
    const int quad  = lane >> 3;
    const int a_row = warp_m * 32 + (quad & 1) * 8 + (lane & 7);
    const int a_cb  = (quad >> 1) * 16;
    const int b_row = warp_n * 64 + (quad >> 1) * 8 + (lane & 7);
    const int b_cb  = (quad & 1) * 16;

    for (int kc = 0; kc < 4; kc++) {
        if (kc < 3) { CP_WAIT(1); } else { CP_WAIT(0); }
        __syncthreads();
        if (kc + 2 <= 3) {
            load_A_stage(sbA, m0, kc + 2, (kc + 2) % 3, tid);
            CP_COMMIT();
        }

        const uint32_t aS = sbA + (uint32_t)(kc % 3) * A_STAGE_BYTES;
        const uint32_t bS = sbB + (uint32_t)kc * B_PANEL_BYTES;

#pragma unroll
        for (int ks = 0; ks < 4; ks++) {
            uint32_t af[2][4], bf[4][4];
#pragma unroll
            for (int t = 0; t < 2; t++) {
                uint32_t off = SWZ((a_row + t * 16) * 128 + ks * 32 + a_cb);
                LDSM_X4(af[t][0], af[t][1], af[t][2], af[t][3], aS + off);
            }
#pragma unroll
            for (int j = 0; j < 4; j++) {
                uint32_t off = SWZ((b_row + j * 16) * 128 + ks * 32 + b_cb);
                LDSM_X4(bf[j][0], bf[j][1], bf[j][2], bf[j][3], bS + off);
            }
#pragma unroll
            for (int t = 0; t < 2; t++)
#pragma unroll
                for (int j = 0; j < 4; j++) {
                    MMA_F16(acc[t][2 * j],     af[t], bf[j][0], bf[j][1]);
                    MMA_F16(acc[t][2 * j + 1], af[t], bf[j][2], bf[j][3]);
                }
        }
    }

    // ---- epilogue: write t tile as fp16 to g_tf
    const int mb = m0 + warp_m * 32;
    const int nb = n0 + warp_n * 64;
    const int r0 = lane >> 2;
    const int c0 = (lane & 3) * 2;
#pragma unroll
    for (int t = 0; t < 2; t++) {
#pragma unroll
        for (int nt = 0; nt < 8; nt++) {
            int col = nb + nt * 8 + c0;
            int row = mb + t * 16 + r0;
            __half2 p01 = __floats2half2_rn(acc[t][nt][0], acc[t][nt][1]);
            __half2 p23 = __floats2half2_rn(acc[t][nt][2], acc[t][nt][3]);
            if (row < N_NODES)
                *reinterpret_cast<__half2*>(&g_tf[(size_t)row * TCOLS + col]) = p01;
            if (row + 8 < N_NODES)
                *reinterpret_cast<__half2*>(&g_tf[(size_t)(row + 8) * TCOLS + col]) = p23;
        }
    }
}

// ===========================================================================
// Kernel 2: per-edge gather + dot + combine.
// 2 edges per warp, each processed by the FULL warp (R8 coalescing pattern),
// with both edges' loads issued up front -> 8 independent coalesced loads.
// ===========================================================================
__device__ __forceinline__ float dot8h(uint4 q, float4 a, float4 b)
{
    float2 f;
    float s;
    f = __half22float2(*reinterpret_cast<__half2*>(&q.x));
    s = fmaf(f.x, a.x, f.y * a.y);
    f = __half22float2(*reinterpret_cast<__half2*>(&q.y));
    s = fmaf(f.x, a.z, fmaf(f.y, a.w, s));
    f = __half22float2(*reinterpret_cast<__half2*>(&q.z));
    s = fmaf(f.x, b.x, fmaf(f.y, b.y, s));
    f = __half22float2(*reinterpret_cast<__half2*>(&q.w));
    s = fmaf(f.x, b.z, fmaf(f.y, b.w, s));
    return s;
}

__global__ __launch_bounds__(256) void edge_bilinear(
    const float* __restrict__ h_dst,
    const int*   __restrict__ u_idx,
    const int*   __restrict__ v_idx,
    const float* __restrict__ W,
    float*       __restrict__ out)
{
    const int warp = (blockIdx.x * blockDim.x + threadIdx.x) >> 5;
    const int lane = threadIdx.x & 31;
    const int e0 = warp * 2;
    const int e1 = e0 + 1;
    if (e0 >= N_EDGES) return;

    const int u0 = u_idx[e0];
    const int v0 = v_idx[e0];
    const int u1 = u_idx[e1];
    const int v1 = v_idx[e1];

    const uint4*  tu0 = reinterpret_cast<const uint4*>(g_tf + (size_t)u0 * TCOLS);
    const uint4*  tu1 = reinterpret_cast<const uint4*>(g_tf + (size_t)u1 * TCOLS);
    const float4* dv0 = reinterpret_cast<const float4*>(h_dst + (size_t)v0 * DIM);
    const float4* dv1 = reinterpret_cast<const float4*>(h_dst + (size_t)v1 * DIM);

    // Edge 0 operands (lane covers k = lane*8..+7, both bases)
    uint4  p0 = tu0[lane];         // basis 0
    uint4  p1 = tu0[lane + 32];    // basis 1
    float4 dA0 = dv0[2 * lane];
    float4 dB0 = dv0[2 * lane + 1];
    // Edge 1 operands
    uint4  q0 = tu1[lane];
    uint4  q1 = tu1[lane + 32];
    float4 dA1 = dv1[2 * lane];
    float4 dB1 = dv1[2 * lane + 1];

    float s00 = dot8h(p0, dA0, dB0);   // edge0 basis0
    float s01 = dot8h(p1, dA0, dB0);   // edge0 basis1
    float s10 = dot8h(q0, dA1, dB1);   // edge1 basis0
    float s11 = dot8h(q1, dA1, dB1);   // edge1 basis1

#pragma unroll
    for (int off = 16; off > 0; off >>= 1) {
        s00 += __shfl_xor_sync(0xFFFFFFFFu, s00, off);
        s01 += __shfl_xor_sync(0xFFFFFFFFu, s01, off);
        s10 += __shfl_xor_sync(0xFFFFFFFFu, s10, off);
        s11 += __shfl_xor_sync(0xFFFFFFFFu, s11, off);
    }

    // lanes 0..7 write edge0, lanes 16..23 write edge1
    const int c = lane & 15;
    if (c < NC && (lane & 8) == 0) {
        float w0 = __ldg(W + c * NB + 0);
        float w1 = __ldg(W + c * NB + 1);
        if (lane < 16)
            out[(size_t)e0 * NC + c] = fmaf(s00, w0, s01 * w1);
        else
            out[(size_t)e1 * NC + c] = fmaf(s10, w0, s11 * w1);
    }
}

// ===========================================================================
// Launch
// ===========================================================================
extern "C" void kernel_launch(void* const* d_in, const int* in_sizes, int n_in,
                              void* d_out, int out_size)
{
    const float* h_src = (const float*)d_in[0];
    const float* h_dst = (const float*)d_in[1];
    const int*   u_idx = (const int*)d_in[2];
    const int*   v_idx = (const int*)d_in[3];
    const float* P     = (const float*)d_in[4];
    const float* W     = (const float*)d_in[5];
    float* out = (float*)d_out;

    cudaFuncSetAttribute(gemm_mma,
                         cudaFuncAttributeMaxDynamicSharedMemorySize,
                         SMEM_TOTAL);

    // 0) fused conversion of A and P to fp16
    prep_fused<<<A_BLOCKS + B_BLOCKS, 256>>>(h_src, P);

    // 1) tensor-core node transform -> g_tf  (grid: n fastest for L2 A-reuse)
    {
        dim3 grid(TCOLS / 128, (N_NODES + 127) / 128);
        gemm_mma<<<grid, 256, SMEM_TOTAL>>>();
    }

    // 2) edge gather + bilinear dot + combine (2 edges/warp, full-warp each)
    {
        int warps = (N_EDGES + 1) / 2;                  // 100000
        int blocks = (warps + 7) / 8;                   // 12500
        edge_bilinear<<<blocks, 256>>>(h_dst, u_idx, v_idx, W, out);
    }
}